// round 1
// baseline (speedup 1.0000x reference)
#include <cuda_runtime.h>
#include <cuda_bf16.h>
#include <cstdint>

// Problem constants (fixed by the dataset's setup_inputs)
#define NNODES 100000
#define NEDGES 50000
#define EDGESZ 16
#define NMEMB  (NEDGES * EDGESZ)   // 800000
#define DIM    128

// Scratch (allocation-free rule: __device__ globals)
__device__ float g_HW2[(size_t)NNODES * DIM];      // H * w2, later reused as AH
__device__ float g_edge_sum[(size_t)NEDGES * DIM];
__device__ float g_acc[(size_t)NNODES * DIM];
__device__ int   g_deg[NNODES];

// ---------------------------------------------------------------------------
// Kernel A: per-node weight MLP, HW2 = H * w2, zero acc/deg
// grid = NNODES blocks, 128 threads
// ---------------------------------------------------------------------------
__global__ void kA(const float* __restrict__ H,
                   const float* __restrict__ iw,
                   const float* __restrict__ fc1w, const float* __restrict__ fc1b,
                   const float* __restrict__ fc2w, const float* __restrict__ fc2b,
                   const float* __restrict__ fc3w, const float* __restrict__ fc3b)
{
    int n = blockIdx.x;
    __shared__ float w2s;
    if (threadIdx.x == 0) {
        float x0 = iw[n * 2 + 0];
        float x1 = iw[n * 2 + 1];
        float h1[10];
#pragma unroll
        for (int j = 0; j < 10; j++)
            h1[j] = fmaxf(0.f, fmaf(x0, fc1w[j], fmaf(x1, fc1w[10 + j], fc1b[j])));
        float h2[5];
#pragma unroll
        for (int j = 0; j < 5; j++) {
            float s = fc2b[j];
#pragma unroll
            for (int k = 0; k < 10; k++) s = fmaf(h1[k], fc2w[k * 5 + j], s);
            h2[j] = fmaxf(0.f, s);
        }
        float z = fc3b[0];
#pragma unroll
        for (int k = 0; k < 5; k++) z = fmaf(h2[k], fc3w[k], z);
        w2s = 1.f / (1.f + __expf(-z) * 0.f + expf(-z) * 1.f); // use precise expf
        g_deg[n] = 0;
    }
    __syncthreads();
    int d = threadIdx.x;
    size_t off = (size_t)n * DIM + d;
    g_HW2[off] = H[off] * w2s;
    g_acc[off] = 0.f;
}

// ---------------------------------------------------------------------------
// Kernel B: per-edge sum of member HW2 rows; also count node degrees
// grid = NEDGES blocks, 128 threads
// ---------------------------------------------------------------------------
__global__ void kB(const int* __restrict__ mn)
{
    int e = blockIdx.x;
    __shared__ int mem[EDGESZ];
    int t = threadIdx.x;
    if (t < EDGESZ) {
        int node = mn[e * EDGESZ + t];
        mem[t] = node;
        atomicAdd(&g_deg[node], 1);
    }
    __syncthreads();
    float s = 0.f;
#pragma unroll
    for (int i = 0; i < EDGESZ; i++)
        s += g_HW2[(size_t)mem[i] * DIM + t];
    g_edge_sum[(size_t)e * DIM + t] = s;
}

// ---------------------------------------------------------------------------
// Kernel C: per-membership scatter-add of edge_sum row into acc[node]
// one warp per membership; lane handles 4 columns
// grid covers NMEMB warps
// ---------------------------------------------------------------------------
__global__ void kC(const int* __restrict__ mn, const int* __restrict__ eid)
{
    int gw = (blockIdx.x * blockDim.x + threadIdx.x) >> 5;
    if (gw >= NMEMB) return;
    int lane = threadIdx.x & 31;
    int node = mn[gw];
    int e = eid[gw];
    const float* es = g_edge_sum + (size_t)e * DIM;
    float* ac = g_acc + (size_t)node * DIM;
#pragma unroll
    for (int j = 0; j < 4; j++) {
        int d = lane + j * 32;
        atomicAdd(ac + d, es[d]);
    }
}

// ---------------------------------------------------------------------------
// Kernel D: new_signal = H*(1-deg/15) + acc/15 ; row-normalize ; store AH
// (reuses g_HW2 as the AH buffer)
// grid = NNODES blocks, 128 threads
// ---------------------------------------------------------------------------
__global__ void kD(const float* __restrict__ H)
{
    int n = blockIdx.x;
    int d = threadIdx.x;
    size_t off = (size_t)n * DIM + d;
    float deg = (float)g_deg[n];
    const float inv15 = 1.f / 15.f;
    float nv = fmaf(H[off], 1.f - deg * inv15, g_acc[off] * inv15);

    // block-wide row sum (128 lanes)
    __shared__ float red[4];
    float v = nv;
#pragma unroll
    for (int o = 16; o > 0; o >>= 1)
        v += __shfl_xor_sync(0xffffffff, v, o);
    if ((threadIdx.x & 31) == 0) red[threadIdx.x >> 5] = v;
    __syncthreads();
    float rowsum = red[0] + red[1] + red[2] + red[3];
    float rinv = (rowsum != 0.f) ? (1.f / rowsum) : 0.f;
    g_HW2[off] = nv * rinv;
}

// ---------------------------------------------------------------------------
// Kernel E: out = AH @ W + bias   (AH in g_HW2)
// block = 128 threads handles 32 nodes; thread owns one output column,
// 32 node-accumulators in registers; AH tile in smem read via broadcast LDS.128
// grid = NNODES/32 blocks
// ---------------------------------------------------------------------------
__global__ __launch_bounds__(128) void kE(const float* __restrict__ W,
                                          const float* __restrict__ bias,
                                          float* __restrict__ out)
{
    __shared__ float sAH[32 * DIM];
    int d = threadIdx.x;
    size_t base = (size_t)blockIdx.x * 32 * DIM;
#pragma unroll
    for (int i = 0; i < 32; i++)
        sAH[i * DIM + d] = g_HW2[base + (size_t)i * DIM + d];
    __syncthreads();

    float acc[32];
#pragma unroll
    for (int i = 0; i < 32; i++) acc[i] = 0.f;

    for (int k = 0; k < DIM; k += 4) {
        float w0 = W[(k + 0) * DIM + d];
        float w1 = W[(k + 1) * DIM + d];
        float w2 = W[(k + 2) * DIM + d];
        float w3 = W[(k + 3) * DIM + d];
#pragma unroll
        for (int i = 0; i < 32; i++) {
            float4 a = *reinterpret_cast<const float4*>(&sAH[i * DIM + k]);
            acc[i] = fmaf(a.x, w0, acc[i]);
            acc[i] = fmaf(a.y, w1, acc[i]);
            acc[i] = fmaf(a.z, w2, acc[i]);
            acc[i] = fmaf(a.w, w3, acc[i]);
        }
    }
    float b = bias[d];
#pragma unroll
    for (int i = 0; i < 32; i++)
        out[base + (size_t)i * DIM + d] = acc[i] + b;
}

// ---------------------------------------------------------------------------
extern "C" void kernel_launch(void* const* d_in, const int* in_sizes, int n_in,
                              void* d_out, int out_size)
{
    const int*   member_nodes = (const int*)  d_in[0];
    const int*   edge_ids     = (const int*)  d_in[1];
    const float* H            = (const float*)d_in[2];
    const float* input_weight = (const float*)d_in[3];
    const float* W            = (const float*)d_in[4];
    const float* bias         = (const float*)d_in[5];
    const float* fc1_w        = (const float*)d_in[6];
    const float* fc1_b        = (const float*)d_in[7];
    const float* fc2_w        = (const float*)d_in[8];
    const float* fc2_b        = (const float*)d_in[9];
    const float* fc3_w        = (const float*)d_in[10];
    const float* fc3_b        = (const float*)d_in[11];
    float* out = (float*)d_out;

    kA<<<NNODES, 128>>>(H, input_weight, fc1_w, fc1_b, fc2_w, fc2_b, fc3_w, fc3_b);
    kB<<<NEDGES, 128>>>(member_nodes);
    {
        // one warp per membership, 256 threads/block => 8 memberships per block
        int blocks = (NMEMB * 32 + 255) / 256;
        kC<<<blocks, 256>>>(member_nodes, edge_ids);
    }
    kD<<<NNODES, 128>>>(H);
    kE<<<NNODES / 32, 128>>>(W, bias, out);
}

// round 2
// speedup vs baseline: 1.4754x; 1.4754x over previous
#include <cuda_runtime.h>
#include <cuda_bf16.h>
#include <cstdint>

// Problem constants (fixed by the dataset's setup_inputs)
#define NNODES 100000
#define NEDGES 50000
#define EDGESZ 16
#define NMEMB  (NEDGES * EDGESZ)   // 800000
#define DIM    128
#define NB_SCAN 98                 // ceil(NNODES / 1024)

// Scratch (allocation-free rule: __device__ globals)
__device__ float g_HW2[(size_t)NNODES * DIM];      // H * w2; later reused as AH
__device__ float g_edge_sum[(size_t)NEDGES * DIM];
__device__ int   g_deg[NNODES];
__device__ int   g_cnt[NNODES];
__device__ int   g_lscan[NNODES];                  // block-local exclusive scan of deg
__device__ int   g_bsum[NB_SCAN];
__device__ int   g_boff[NB_SCAN];                  // exclusive scan of block sums
__device__ int   g_elist[NMEMB];                   // node -> list of incident edges

// ---------------------------------------------------------------------------
// packed f32x2 helpers
// ---------------------------------------------------------------------------
__device__ __forceinline__ void fma2(unsigned long long& d,
                                     unsigned long long a, unsigned long long b)
{
    asm("fma.rn.f32x2 %0, %1, %2, %0;" : "+l"(d) : "l"(a), "l"(b));
}
__device__ __forceinline__ unsigned long long pk2(float lo, float hi)
{
    unsigned long long r;
    asm("mov.b64 %0, {%1, %2};" : "=l"(r) : "f"(lo), "f"(hi));
    return r;
}
__device__ __forceinline__ void unpk2(float& lo, float& hi, unsigned long long v)
{
    asm("mov.b64 {%0, %1}, %2;" : "=f"(lo), "=f"(hi) : "l"(v));
}

// ---------------------------------------------------------------------------
// Kernel A: per-node weight MLP (parallel across threads), HW2 = H * w2,
// zero deg/cnt. grid = ceil(NNODES/128) blocks x 128 threads.
// ---------------------------------------------------------------------------
__global__ __launch_bounds__(128) void kA(
    const float* __restrict__ H, const float* __restrict__ iw,
    const float* __restrict__ fc1w, const float* __restrict__ fc1b,
    const float* __restrict__ fc2w, const float* __restrict__ fc2b,
    const float* __restrict__ fc3w, const float* __restrict__ fc3b)
{
    __shared__ float w2s[128];
    int t = threadIdx.x;
    int base = blockIdx.x * 128;
    int n = base + t;
    if (n < NNODES) {
        float x0 = iw[n * 2 + 0];
        float x1 = iw[n * 2 + 1];
        float h1[10];
#pragma unroll
        for (int j = 0; j < 10; j++)
            h1[j] = fmaxf(0.f, fmaf(x0, fc1w[j], fmaf(x1, fc1w[10 + j], fc1b[j])));
        float h2[5];
#pragma unroll
        for (int j = 0; j < 5; j++) {
            float s = fc2b[j];
#pragma unroll
            for (int k = 0; k < 10; k++) s = fmaf(h1[k], fc2w[k * 5 + j], s);
            h2[j] = fmaxf(0.f, s);
        }
        float z = fc3b[0];
#pragma unroll
        for (int k = 0; k < 5; k++) z = fmaf(h2[k], fc3w[k], z);
        w2s[t] = 1.f / (1.f + expf(-z));
        g_deg[n] = 0;
        g_cnt[n] = 0;
    }
    __syncthreads();
    int nmax = NNODES - base;   // nodes valid in this block
#pragma unroll 4
    for (int i = 0; i < 128; i++) {
        if (i >= nmax) break;
        size_t off = (size_t)(base + i) * DIM + t;
        g_HW2[off] = H[off] * w2s[i];
    }
}

// ---------------------------------------------------------------------------
// Kernel B: per-edge sum of member HW2 rows; node-degree histogram
// grid = NEDGES blocks x 128 threads
// ---------------------------------------------------------------------------
__global__ __launch_bounds__(128) void kB(const int* __restrict__ mn)
{
    int e = blockIdx.x;
    __shared__ int mem[EDGESZ];
    int t = threadIdx.x;
    if (t < EDGESZ) {
        int node = mn[e * EDGESZ + t];
        mem[t] = node;
        atomicAdd(&g_deg[node], 1);
    }
    __syncthreads();
    float s = 0.f;
#pragma unroll
    for (int i = 0; i < EDGESZ; i++)
        s += g_HW2[(size_t)mem[i] * DIM + t];
    g_edge_sum[(size_t)e * DIM + t] = s;
}

// ---------------------------------------------------------------------------
// Scan stage 1: per-1024-block exclusive scan of g_deg, plus block totals
// ---------------------------------------------------------------------------
__global__ __launch_bounds__(1024) void s1()
{
    int b = blockIdx.x, t = threadIdx.x;
    int idx = b * 1024 + t;
    int v = (idx < NNODES) ? g_deg[idx] : 0;
    int lane = t & 31, w = t >> 5;
    int x = v;
#pragma unroll
    for (int o = 1; o < 32; o <<= 1) {
        int y = __shfl_up_sync(0xffffffff, x, o);
        if (lane >= o) x += y;
    }
    __shared__ int wt[32];
    if (lane == 31) wt[w] = x;
    __syncthreads();
    if (w == 0) {
        int z = wt[lane];
#pragma unroll
        for (int o = 1; o < 32; o <<= 1) {
            int y = __shfl_up_sync(0xffffffff, z, o);
            if (lane >= o) z += y;
        }
        wt[lane] = z;
    }
    __syncthreads();
    int incl = x + (w ? wt[w - 1] : 0);
    if (idx < NNODES) g_lscan[idx] = incl - v;
    if (t == 1023) g_bsum[b] = incl;
}

// ---------------------------------------------------------------------------
// Scan stage 2: exclusive scan of NB_SCAN block sums (single block)
// ---------------------------------------------------------------------------
__global__ __launch_bounds__(128) void s2()
{
    int t = threadIdx.x;
    __shared__ int s[128];
    int v = (t < NB_SCAN) ? g_bsum[t] : 0;
    s[t] = v;
    __syncthreads();
#pragma unroll
    for (int o = 1; o < 128; o <<= 1) {
        int x = s[t];
        if (t >= o) x += s[t - o];
        __syncthreads();
        s[t] = x;
        __syncthreads();
    }
    if (t < NB_SCAN) g_boff[t] = s[t] - v;
}

// ---------------------------------------------------------------------------
// Scatter: build node -> incident-edge list
// ---------------------------------------------------------------------------
__global__ void kScat(const int* __restrict__ mn, const int* __restrict__ eid)
{
    int m = blockIdx.x * blockDim.x + threadIdx.x;
    if (m >= NMEMB) return;
    int node = mn[m];
    int pos = g_lscan[node] + g_boff[node >> 10] + atomicAdd(&g_cnt[node], 1);
    g_elist[pos] = eid[m];
}

// ---------------------------------------------------------------------------
// Fused gather + new_signal + row-normalize -> AH (stored into g_HW2)
// grid = NNODES blocks x 128 threads
// ---------------------------------------------------------------------------
__global__ __launch_bounds__(128) void kF(const float* __restrict__ H)
{
    int n = blockIdx.x, t = threadIdx.x;
    int start = g_lscan[n] + g_boff[n >> 10];
    int deg = g_deg[n];
    float s = 0.f;
    for (int i = 0; i < deg; i++) {
        int e = __ldg(&g_elist[start + i]);
        s += g_edge_sum[(size_t)e * DIM + t];
    }
    size_t off = (size_t)n * DIM + t;
    const float inv15 = 1.f / 15.f;
    float nv = fmaf(H[off], 1.f - (float)deg * inv15, s * inv15);

    // block-wide row sum
    __shared__ float red[4];
    float v = nv;
#pragma unroll
    for (int o = 16; o > 0; o >>= 1)
        v += __shfl_xor_sync(0xffffffff, v, o);
    if ((t & 31) == 0) red[t >> 5] = v;
    __syncthreads();
    float rowsum = red[0] + red[1] + red[2] + red[3];
    float rinv = (rowsum != 0.f) ? (1.f / rowsum) : 0.f;
    g_HW2[off] = nv * rinv;
}

// ---------------------------------------------------------------------------
// Kernel E: out = AH @ W + bias (AH in g_HW2), packed f32x2 FFMA
// block = 128 threads handles 32 nodes; thread owns one output column.
// Accumulator packs {even-k partial, odd-k partial}; halves added at the end.
// ---------------------------------------------------------------------------
__global__ __launch_bounds__(128) void kE(const float* __restrict__ W,
                                          const float* __restrict__ bias,
                                          float* __restrict__ out)
{
    __shared__ float sAH[32 * DIM];
    int d = threadIdx.x;
    size_t base = (size_t)blockIdx.x * 32 * DIM;
#pragma unroll
    for (int i = 0; i < 32; i++)
        sAH[i * DIM + d] = g_HW2[base + (size_t)i * DIM + d];
    __syncthreads();

    unsigned long long acc[32];
#pragma unroll
    for (int i = 0; i < 32; i++) acc[i] = 0ull;

#pragma unroll 1
    for (int k = 0; k < DIM; k += 4) {
        float w0 = W[(k + 0) * DIM + d];
        float w1 = W[(k + 1) * DIM + d];
        float w2 = W[(k + 2) * DIM + d];
        float w3 = W[(k + 3) * DIM + d];
        unsigned long long wp01 = pk2(w0, w1);
        unsigned long long wp23 = pk2(w2, w3);
        const unsigned long long* arow =
            reinterpret_cast<const unsigned long long*>(sAH + k);
#pragma unroll
        for (int i = 0; i < 32; i++) {
            unsigned long long a01 = arow[i * (DIM / 2) + 0];
            unsigned long long a23 = arow[i * (DIM / 2) + 1];
            fma2(acc[i], a01, wp01);
            fma2(acc[i], a23, wp23);
        }
    }
    float b = bias[d];
#pragma unroll
    for (int i = 0; i < 32; i++) {
        float lo, hi;
        unpk2(lo, hi, acc[i]);
        out[base + (size_t)i * DIM + d] = lo + hi + b;
    }
}

// ---------------------------------------------------------------------------
extern "C" void kernel_launch(void* const* d_in, const int* in_sizes, int n_in,
                              void* d_out, int out_size)
{
    const int*   member_nodes = (const int*)  d_in[0];
    const int*   edge_ids     = (const int*)  d_in[1];
    const float* H            = (const float*)d_in[2];
    const float* input_weight = (const float*)d_in[3];
    const float* W            = (const float*)d_in[4];
    const float* bias         = (const float*)d_in[5];
    const float* fc1_w        = (const float*)d_in[6];
    const float* fc1_b        = (const float*)d_in[7];
    const float* fc2_w        = (const float*)d_in[8];
    const float* fc2_b        = (const float*)d_in[9];
    const float* fc3_w        = (const float*)d_in[10];
    const float* fc3_b        = (const float*)d_in[11];
    float* out = (float*)d_out;

    kA<<<(NNODES + 127) / 128, 128>>>(H, input_weight,
                                      fc1_w, fc1_b, fc2_w, fc2_b, fc3_w, fc3_b);
    kB<<<NEDGES, 128>>>(member_nodes);
    s1<<<NB_SCAN, 1024>>>();
    s2<<<1, 128>>>();
    kScat<<<(NMEMB + 255) / 256, 256>>>(member_nodes, edge_ids);
    kF<<<NNODES, 128>>>(H);
    kE<<<NNODES / 32, 128>>>(W, bias, out);
}